// round 16
// baseline (speedup 1.0000x reference)
#include <cuda_runtime.h>
#include <math.h>

#define B_    64
#define T_    512
#define EMB_  256
#define HD_   256
#define TAGS_ 11
#define NEGV  (-10000.0f)

// ---------------- scratch (static device globals; no allocs) ----------------
__device__ __align__(16) float g_Hout[(long)2 * T_ * B_ * HD_]; // [dir][t][unit][b]
__device__ __align__(16) float g_hbuf[2 * 2 * B_ * HD_];        // [dir][buf][b][k]
__device__ __align__(16) float g_feats[T_ * B_ * TAGS_];
#define LSTM_NB 256
#define FPAD 32   // one flag per 128B cache line
__device__ __align__(128) unsigned g_flags[LSTM_NB * FPAD];     // monotonic epochs

// ---------------- packed f32x2 helpers ----------------
__device__ __forceinline__ void ffma2(unsigned long long& d,
                                      unsigned long long a,
                                      unsigned long long b) {
    asm("fma.rn.f32x2 %0, %1, %2, %0;" : "+l"(d) : "l"(a), "l"(b));
}
__device__ __forceinline__ float2 upk(unsigned long long v) {
    float2 f; asm("mov.b64 {%0, %1}, %2;" : "=f"(f.x), "=f"(f.y) : "l"(v)); return f;
}

// ---------------- fast activations (MUFU-based, ~1e-6 rel err) ----------------
__device__ __forceinline__ float sigf(float x) {
    return __fdividef(1.f, 1.f + __expf(-x));
}
__device__ __forceinline__ float tanhfast(float x) {
    return fmaf(2.f, __fdividef(1.f, 1.f + __expf(-2.f * x)), -1.f);
}

// ---------------- release/acquire flag ops ----------------
__device__ __forceinline__ unsigned ld_acq(const unsigned* p) {
    unsigned v;
    asm volatile("ld.global.acquire.gpu.u32 %0, [%1];" : "=r"(v) : "l"(p));
    return v;
}
__device__ __forceinline__ void st_rel(unsigned* p, unsigned v) {
    asm volatile("st.global.release.gpu.u32 [%0], %1;" :: "l"(p), "r"(v) : "memory");
}

// =====================================================================
// K2: persistent FUSED bidirectional LSTM, 256 CTAs x 128 threads, 2/SM.
// CTA = (dir, ug = 8-unit group 0..31, bg = 16-batch group 0..3).
// thread: b_loc = tid&15, u_loc = tid>>4 (0..7).
// Per step: [input dot for t computed LAST iteration while producers ran]
//   wait 32 flags (16+16 half-split), stage 16KB h, recurrent dot
//   accumulating onto input dot, gates, publish, release;
//   then gather x[t+1] from embed (L2-resident) + input dot for t+1.
// smem: Whh 32x260 | Wih 32x260 | x 16x260 | h 16x260 = 99,840 B
// =====================================================================
#define WST       260
#define SM_WHH    0
#define SM_WIH    (32 * WST)
#define SM_X      (64 * WST)
#define SM_H      (80 * WST)
#define LSTM_SMEM (96 * WST * 4)   // 99,840 B

__global__ void __launch_bounds__(128, 2)
lstm_kernel(const int* __restrict__ sent,
            const float* __restrict__ embed,
            const float* __restrict__ Wih_f, const float* __restrict__ b_f,
            const float* __restrict__ Wih_b, const float* __restrict__ b_b,
            const float* __restrict__ Whh_f, const float* __restrict__ Whh_b,
            const float* __restrict__ h0f, const float* __restrict__ c0f,
            const float* __restrict__ h0b, const float* __restrict__ c0b,
            const float* __restrict__ mask)
{
    extern __shared__ __align__(16) float sm[];
    float* Whs = sm + SM_WHH;   // [g*8+u_loc][k] stride WST
    float* Wis = sm + SM_WIH;   // [g*8+u_loc][k]
    float* xsm = sm + SM_X;     // [b_loc][k]
    float* hsm = sm + SM_H;     // [b_loc][k]

    const int cta  = blockIdx.x;
    const int dir  = cta >> 7;
    const int ug   = (cta & 127) >> 2;  // 0..31
    const int bg   = cta & 3;           // 0..3
    const int tid  = threadIdx.x;
    const int b_loc = tid & 15;
    const int u_loc = tid >> 4;         // 0..7
    const int unit = ug * 8 + u_loc;
    const int b    = bg * 16 + b_loc;

    const float* __restrict__ Whh = dir ? Whh_b : Whh_f;
    const float* __restrict__ Wih = dir ? Wih_b : Wih_f;
    const float* __restrict__ bias = dir ? b_b : b_f;
    const float* __restrict__ h0  = dir ? h0b : h0f;
    const float* __restrict__ c0  = dir ? c0b : c0f;

    float* hbuf0 = g_hbuf + (dir * 2 + 0) * (64 * 256);   // [b][k]
    float* hbuf1 = g_hbuf + (dir * 2 + 1) * (64 * 256);
    float* HoutD = g_Hout + (long)dir * T_ * 64 * 256;    // [t][unit][b]
    unsigned* myflag = &g_flags[cta * FPAD];
    const unsigned* pflag_base = &g_flags[(dir * 128 + bg) * FPAD];

    __shared__ unsigned sbase;
    if (tid == 0) sbase = ld_acq(myflag);
    __syncthreads();
    const unsigned base = sbase;

    float c = c0[b * HD_ + unit];
    float h = h0[b * HD_ + unit];

    // EARLY initial publish (before heavy preloads) so step-0 waits are short
    __stcg(hbuf0 + b * 256 + unit, h);
    __syncthreads();
    if (tid == 0) st_rel(myflag, base + 1);

    // preload weight slices: rows g*8+uu = W[g*256 + ug*8+uu][k]
#pragma unroll
    for (int i = 0; i < 16; i++) {
        int f  = tid + i * 128;       // float4 idx 0..2047
        int r  = f >> 6;              // 0..31
        int k4 = f & 63;
        int grow = (r >> 3) * 256 + ug * 8 + (r & 7);
        *(float4*)&Whs[r * WST + k4 * 4] = *(const float4*)(Whh + (long)grow * HD_ + k4 * 4);
        *(float4*)&Wis[r * WST + k4 * 4] = *(const float4*)(Wih + (long)grow * EMB_ + k4 * 4);
    }
    const float bi0 = bias[0 * 256 + unit];
    const float bi1 = bias[1 * 256 + unit];
    const float bi2 = bias[2 * 256 + unit];
    const float bi3 = bias[3 * 256 + unit];

    const float* w0p = &Whs[(0 * 8 + u_loc) * WST];
    const float* w1p = &Whs[(1 * 8 + u_loc) * WST];
    const float* w2p = &Whs[(2 * 8 + u_loc) * WST];
    const float* w3p = &Whs[(3 * 8 + u_loc) * WST];
    const float* i0p = &Wis[(0 * 8 + u_loc) * WST];
    const float* i1p = &Wis[(1 * 8 + u_loc) * WST];
    const float* i2p = &Wis[(2 * 8 + u_loc) * WST];
    const float* i3p = &Wis[(3 * 8 + u_loc) * WST];
    const float* hrow = &hsm[b_loc * WST];
    const float* xrow = &xsm[b_loc * WST];

    unsigned long long a0p, a1p, a2p, a3p;

#define DOT(K0, K1, ROW, P0, P1, P2, P3)                               \
    _Pragma("unroll 8")                                                \
    for (int kk = (K0); kk < (K1); kk++) {                             \
        ulonglong2 hv = *(const ulonglong2*)&(ROW)[kk * 4];            \
        ulonglong2 w0 = *(const ulonglong2*)&(P0)[kk * 4];             \
        ulonglong2 w1 = *(const ulonglong2*)&(P1)[kk * 4];             \
        ulonglong2 w2 = *(const ulonglong2*)&(P2)[kk * 4];             \
        ulonglong2 w3 = *(const ulonglong2*)&(P3)[kk * 4];             \
        ffma2(a0p, hv.x, w0.x); ffma2(a0p, hv.y, w0.y);                \
        ffma2(a1p, hv.x, w1.x); ffma2(a1p, hv.y, w1.y);                \
        ffma2(a2p, hv.x, w2.x); ffma2(a2p, hv.y, w2.y);                \
        ffma2(a3p, hv.x, w3.x); ffma2(a3p, hv.y, w3.y);                \
    }

    // gather x[t0] + input dot for step 0
    const int t0 = dir ? (T_ - 1) : 0;
#pragma unroll
    for (int i = 0; i < 8; i++) {
        int e = tid + i * 128;        // 0..1023 float4 units
        int row = e >> 6, c4 = e & 63;
        int tok = __ldg(sent + (bg * 16 + row) * T_ + t0);
        *(float4*)&xsm[row * WST + c4 * 4] =
            __ldg((const float4*)(embed + (long)tok * EMB_ + c4 * 4));
    }
    __syncthreads();
    a0p = a1p = a2p = a3p = 0ull;
    DOT(0, 64, xrow, i0p, i1p, i2p, i3p)
    float mt = __ldg(mask + t0 * B_ + b);

    for (int s = 0; s < T_; s++) {
        const int t = dir ? (T_ - 1 - s) : s;
        const int p = s & 1;
        const float4* hin = (const float4*)((p ? hbuf1 : hbuf0) + bg * 16 * 256);

        // ---- first half: producers ug' 0..15 (k 0..127) ----
        if (tid < 16) {
            const unsigned* f = pflag_base + tid * 4 * FPAD;
            while ((int)(ld_acq(f) - base) < (int)(s + 1)) { }
        }
        __syncthreads();
#pragma unroll
        for (int i = 0; i < 4; i++) {
            int e = tid + i * 128;          // 0..511
            int row = e >> 5, c4 = e & 31;
            *(float4*)&hsm[row * WST + c4 * 4] = __ldcg(hin + row * 64 + c4);
        }
        __syncthreads();
        DOT(0, 32, hrow, w0p, w1p, w2p, w3p)

        // ---- second half: producers ug' 16..31 (k 128..255) ----
        if (tid >= 16 && tid < 32) {
            const unsigned* f = pflag_base + tid * 4 * FPAD;
            while ((int)(ld_acq(f) - base) < (int)(s + 1)) { }
        }
        __syncthreads();
#pragma unroll
        for (int i = 0; i < 4; i++) {
            int e = tid + i * 128;
            int row = e >> 5, c4 = 32 + (e & 31);
            *(float4*)&hsm[row * WST + c4 * 4] = __ldcg(hin + row * 64 + c4);
        }
        __syncthreads();
        DOT(32, 64, hrow, w0p, w1p, w2p, w3p)

        float2 q0 = upk(a0p), q1 = upk(a1p), q2 = upk(a2p), q3 = upk(a3p);
        float a0 = bi0 + q0.x + q0.y;
        float a1 = bi1 + q1.x + q1.y;
        float a2 = bi2 + q2.x + q2.y;
        float a3 = bi3 + q3.x + q3.y;

        float si = sigf(a0);
        float sf = sigf(a1);
        float tg = tanhfast(a2);
        float so = sigf(a3);
        float cn = sf * c + si * tg;
        float hn = so * tanhfast(cn);
        h = mt * hn + (1.f - mt) * h;
        c = mt * cn + (1.f - mt) * c;

        // publish, then flag release
        __stcg((p ? hbuf0 : hbuf1) + b * 256 + unit, h);
        __syncthreads();
        if (tid == 0) st_rel(myflag, base + s + 2);

        // Hout store — off the critical path
        HoutD[((long)t * 256 + unit) * 64 + b] = h;

        // gather x + input dot for NEXT step (fills producer slack)
        if (s + 1 < T_) {
            const int tn = dir ? (T_ - 2 - s) : (s + 1);
#pragma unroll
            for (int i = 0; i < 8; i++) {
                int e = tid + i * 128;
                int row = e >> 6, c4 = e & 63;
                int tok = __ldg(sent + (bg * 16 + row) * T_ + tn);
                *(float4*)&xsm[row * WST + c4 * 4] =
                    __ldg((const float4*)(embed + (long)tok * EMB_ + c4 * 4));
            }
            __syncthreads();
            a0p = a1p = a2p = a3p = 0ull;
            DOT(0, 64, xrow, i0p, i1p, i2p, i3p)
            mt = __ldg(mask + tn * B_ + b);
        }
    }
#undef DOT
}

// =====================================================================
// K3: feats[t][b][j] = (sum_k (h[k]*m) * Wtag[j][k] + btag[j]) * m
// =====================================================================
__global__ void feats_kernel(const float* __restrict__ Wtag,
                             const float* __restrict__ btag,
                             const float* __restrict__ mask)
{
    __shared__ float Ws[TAGS_ * 512];
    __shared__ float bts[TAGS_];
    const int t   = blockIdx.x;
    const int tid = threadIdx.x;
    for (int i = tid; i < TAGS_ * 512; i += 256) Ws[i] = Wtag[i];
    if (tid < TAGS_) bts[tid] = btag[tid];
    __syncthreads();

    const int w    = tid >> 5;
    const int lane = tid & 31;
    const float* Hf = g_Hout + ((long)t * 256) * 64;
    const float* Hb = g_Hout + ((long)T_ * 256 + (long)t * 256) * 64;
    for (int b = w; b < B_; b += 8) {
        float mt = mask[t * B_ + b];
        float acc[TAGS_];
#pragma unroll
        for (int j = 0; j < TAGS_; j++) acc[j] = 0.f;
        for (int k = lane; k < HD_; k += 32) {
            float hv  = Hf[k * 64 + b] * mt;
            float hv2 = Hb[k * 64 + b] * mt;
#pragma unroll
            for (int j = 0; j < TAGS_; j++) {
                acc[j] = fmaf(hv,  Ws[j * 512 + k],       acc[j]);
                acc[j] = fmaf(hv2, Ws[j * 512 + HD_ + k], acc[j]);
            }
        }
#pragma unroll
        for (int j = 0; j < TAGS_; j++)
#pragma unroll
            for (int off = 16; off > 0; off >>= 1)
                acc[j] += __shfl_xor_sync(0xffffffffu, acc[j], off);
        if (lane < TAGS_)
            g_feats[(t * B_ + b) * TAGS_ + lane] = (acc[lane] + bts[lane]) * mt;
    }
}

// =====================================================================
// K4: Viterbi. 1 CTA/batch. fmax-tree chain, off-chain argmax.
// =====================================================================
__global__ void viterbi_kernel(const float* __restrict__ trans,
                               const float* __restrict__ mask,
                               float* __restrict__ out, int out_size)
{
    __shared__ float fsh[T_ * TAGS_];
    __shared__ float msh[T_];
    __shared__ unsigned char ptrs[T_ * TAGS_];
    __shared__ float trs[TAGS_ * TAGS_];
    const int bb  = blockIdx.x;
    const int tid = threadIdx.x;   // 128

    for (int i = tid; i < T_ * TAGS_; i += 128) {
        int t = i / TAGS_, j = i % TAGS_;
        fsh[i] = g_feats[(t * B_ + bb) * TAGS_ + j];
    }
    for (int i = tid; i < T_; i += 128) msh[i] = mask[i * B_ + bb];
    for (int i = tid; i < TAGS_ * TAGS_; i += 128) trs[i] = trans[i];
    __syncthreads();
    if (tid >= 32) return;

    const int j  = tid;
    const int jc = (j < TAGS_) ? j : 0;
    float trow[TAGS_];
#pragma unroll
    for (int q = 0; q < TAGS_; q++) trow[q] = trs[jc * TAGS_ + q];

    float s[TAGS_];
#pragma unroll
    for (int q = 0; q < TAGS_; q++) s[q] = (q == 9) ? 0.f : NEGV;   // START=9

    for (int t = 0; t < T_; t++) {
        float ft = fsh[t * TAGS_ + jc];
        float mt = msh[t];

        float v[TAGS_];
#pragma unroll
        for (int q = 0; q < TAGS_; q++) v[q] = s[q] + trow[q];

        float m0 = fmaxf(v[0], v[1]);
        float m1 = fmaxf(v[2], v[3]);
        float m2 = fmaxf(v[4], v[5]);
        float m3 = fmaxf(v[6], v[7]);
        float m4 = fmaxf(v[8], v[9]);
        float n0 = fmaxf(m0, m1);
        float n1 = fmaxf(m2, m3);
        float n2 = fmaxf(m4, v[10]);
        float best = fmaxf(fmaxf(n0, n1), n2);

        int arg = 10;
#pragma unroll
        for (int q = 9; q >= 0; q--) arg = (v[q] == best) ? q : arg;
        if (j < TAGS_) ptrs[t * TAGS_ + j] = (unsigned char)arg;

        float ns = best + ft;
        float sn = (mt > 0.f) ? ns : s[jc];
#pragma unroll
        for (int q = 0; q < TAGS_; q++)
            s[q] = __shfl_sync(0xffffffffu, sn, q);
    }

    float fv[TAGS_];
#pragma unroll
    for (int q = 0; q < TAGS_; q++) fv[q] = s[q] + trs[10 * TAGS_ + q];   // STOP=10
    float fb = fv[0];
#pragma unroll
    for (int q = 1; q < TAGS_; q++) fb = fmaxf(fb, fv[q]);
    int fbt = 10;
#pragma unroll
    for (int q = 9; q >= 0; q--) fbt = (fv[q] == fb) ? q : fbt;

    if (tid == 0) {
        if (out_size >= B_ * T_ + B_) out[B_ * T_ + bb] = fb;
        int cur = fbt;
        for (int t = T_ - 1; t >= 0; t--) {
            if (bb * T_ + t < out_size) out[bb * T_ + t] = (float)cur;
            cur = ptrs[t * TAGS_ + cur];
        }
    }
}

// =====================================================================
extern "C" void kernel_launch(void* const* d_in, const int* in_sizes, int n_in,
                              void* d_out, int out_size)
{
    const int*   sent  = (const int*)d_in[0];
    const float* mask  = (const float*)d_in[1];
    const float* embed = (const float*)d_in[2];
    const float* Wih_f = (const float*)d_in[3];
    const float* Whh_f = (const float*)d_in[4];
    const float* b_f   = (const float*)d_in[5];
    const float* Wih_b = (const float*)d_in[6];
    const float* Whh_b = (const float*)d_in[7];
    const float* b_b   = (const float*)d_in[8];
    const float* h0f   = (const float*)d_in[9];
    const float* c0f   = (const float*)d_in[10];
    const float* h0b   = (const float*)d_in[11];
    const float* c0b   = (const float*)d_in[12];
    const float* Wtag  = (const float*)d_in[13];
    const float* btag  = (const float*)d_in[14];
    const float* trans = (const float*)d_in[15];

    cudaFuncSetAttribute(lstm_kernel, cudaFuncAttributeMaxDynamicSharedMemorySize, LSTM_SMEM);
    lstm_kernel<<<LSTM_NB, 128, LSTM_SMEM>>>(sent, embed,
                                             Wih_f, b_f, Wih_b, b_b,
                                             Whh_f, Whh_b,
                                             h0f, c0f, h0b, c0b, mask);

    feats_kernel<<<T_, 256>>>(Wtag, btag, mask);

    viterbi_kernel<<<B_, 128>>>(trans, mask, (float*)d_out, out_size);
}